// round 15
// baseline (speedup 1.0000x reference)
#include <cuda_runtime.h>
#include <cstdint>

// Fused HybridSamplerConv, round 14: TMA bulk-copy pipeline.
// 13 rounds established: LDG streaming is register-bound — in-flight bytes
// (regs x warps) sit exactly at the Little's-law floor and every reg/occ
// trade loses. cp.async.bulk breaks the coupling: in-flight data lives in
// SMEM (3 stages x 24KB per CTA), tracked by mbarrier, zero register cost.
// Persistent CTAs; consumers compute from SMEM with the proven math body.

#define THREADS        256
#define STAGES         3
#define TILE_SAMPLES   1024              // per tile
#define INP_BYTES      (TILE_SAMPLES * 8)    // 8192
#define DATA_BYTES     (TILE_SAMPLES * 16)   // 16384
#define STAGE_BYTES    (INP_BYTES + DATA_BYTES) // 24576
#define SMEM_DATA_OFF  128               // barriers live in [0,128)
#define SMEM_TOTAL     (SMEM_DATA_OFF + STAGES * STAGE_BYTES)

__device__ __forceinline__ uint32_t smem_u32(const void* p) {
    uint32_t a;
    asm("{ .reg .u64 t; cvta.to.shared.u64 t, %1; cvt.u32.u64 %0, t; }"
        : "=r"(a) : "l"(p));
    return a;
}

__device__ __forceinline__ void mbar_init(uint32_t mbar, uint32_t count) {
    asm volatile("mbarrier.init.shared.b64 [%0], %1;" :: "r"(mbar), "r"(count) : "memory");
}

__device__ __forceinline__ void mbar_expect_tx(uint32_t mbar, uint32_t bytes) {
    asm volatile("mbarrier.arrive.expect_tx.shared.b64 _, [%0], %1;"
                 :: "r"(mbar), "r"(bytes) : "memory");
}

__device__ __forceinline__ void bulk_g2s(uint32_t smem_dst, const void* gmem_src,
                                         uint32_t bytes, uint32_t mbar) {
    asm volatile("cp.async.bulk.shared::cta.global.mbarrier::complete_tx::bytes "
                 "[%0], [%1], %2, [%3];"
                 :: "r"(smem_dst), "l"(gmem_src), "r"(bytes), "r"(mbar) : "memory");
}

__device__ __forceinline__ void mbar_wait(uint32_t mbar, uint32_t parity) {
    asm volatile(
        "{\n\t"
        ".reg .pred P;\n\t"
        "WAIT_%=: \n\t"
        "mbarrier.try_wait.parity.acquire.cta.shared::cta.b64 P, [%0], %1, 0x989680;\n\t"
        "@P bra.uni DONE_%=;\n\t"
        "bra.uni WAIT_%=;\n\t"
        "DONE_%=: \n\t"
        "}"
        :: "r"(mbar), "r"(parity) : "memory");
}

__device__ __forceinline__ float tanh_fast(float x) {
    float y;
    asm("tanh.approx.f32 %0, %1;" : "=f"(y) : "f"(x));
    return y;
}

__global__ void __launch_bounds__(THREADS)
hybrid_sampler_kernel(const float4* __restrict__ inp,    // [B/2]
                      const float4* __restrict__ data,   // [B]
                      const float4* __restrict__ conv_w,
                      const float*  __restrict__ conv_b,
                      const float4* __restrict__ w1v,
                      const float4* __restrict__ b1v,
                      const float4* __restrict__ w2v,
                      const float2* __restrict__ b2v,
                      float4*       __restrict__ out,    // [B/2]
                      int ntiles)
{
    extern __shared__ char smem[];
    const uint32_t sbase = smem_u32(smem);
    const uint32_t mbar0 = sbase;                 // 3 x 8B barriers
    const int tid = threadIdx.x;

    if (tid == 0) {
#pragma unroll
        for (int s = 0; s < STAGES; ++s) mbar_init(mbar0 + 8u * s, 1);
        // make barrier init visible to the async proxy before first bulk copy
        asm volatile("fence.proxy.async.shared::cta;" ::: "memory");
    }
    __syncthreads();

    // ---- uniform params (loaded once per thread, L1-broadcast) ----
    float4 cw   = __ldg(conv_w);
    float  cb   = __ldg(conv_b);
    float4 w1r0 = __ldg(w1v + 0);
    float4 w1r1 = __ldg(w1v + 1);
    float4 w1r2 = __ldg(w1v + 2);
    float4 b1   = __ldg(b1v);
    float g0, g1, g2, g3, gb;
    {
        float4 w2a = __ldg(w2v + 0);
        float4 w2b = __ldg(w2v + 1);
        float2 b2  = __ldg(b2v);
        g0 = w2a.y - w2a.x;
        g1 = w2a.w - w2a.z;
        g2 = w2b.y - w2b.x;
        g3 = w2b.w - w2b.z;
        gb = b2.y  - b2.x;
    }

    // ---- prologue: fill the pipeline ----
    if (tid == 0) {
#pragma unroll
        for (int s = 0; s < STAGES; ++s) {
            int t = blockIdx.x + s * gridDim.x;
            if (t < ntiles) {
                uint32_t mb = mbar0 + 8u * s;
                uint32_t dst = sbase + SMEM_DATA_OFF + s * STAGE_BYTES;
                mbar_expect_tx(mb, STAGE_BYTES);
                bulk_g2s(dst,             inp  + (size_t)t * (TILE_SAMPLES / 2), INP_BYTES,  mb);
                bulk_g2s(dst + INP_BYTES, data + (size_t)t * TILE_SAMPLES,       DATA_BYTES, mb);
            }
        }
    }

    // ---- main loop over this CTA's tiles ----
    int iter = 0;
    for (int tile = blockIdx.x; tile < ntiles; tile += gridDim.x, ++iter) {
        int s = iter % STAGES;
        uint32_t parity = (uint32_t)((iter / STAGES) & 1);
        mbar_wait(mbar0 + 8u * s, parity);

        const float4* sinp = (const float4*)(smem + SMEM_DATA_OFF + s * STAGE_BYTES);
        const float4* sdat = (const float4*)(smem + SMEM_DATA_OFF + s * STAGE_BYTES + INP_BYTES);

        float4 inA = sinp[2 * tid + 0];
        float4 inB = sinp[2 * tid + 1];
        float4 d0  = sdat[4 * tid + 0];
        float4 d1  = sdat[4 * tid + 1];
        float4 d2  = sdat[4 * tid + 2];
        float4 d3  = sdat[4 * tid + 3];

        float4 resA, resB;
#pragma unroll
        for (int q = 0; q < 4; ++q) {
            float in0, in1;
            float4 d;
            if      (q == 0) { in0 = inA.x; in1 = inA.y; d = d0; }
            else if (q == 1) { in0 = inA.z; in1 = inA.w; d = d1; }
            else if (q == 2) { in0 = inB.x; in1 = inB.y; d = d2; }
            else             { in0 = inB.z; in1 = inB.w; d = d3; }

            float logit = fmaf(d.x, cw.x, fmaf(d.y, cw.y,
                          fmaf(d.z, cw.z, fmaf(d.w, cw.w, cb))));
            float conv = fmaf(tanh_fast(0.5f * logit), 0.5f, 0.5f);

            float h0 = tanh_fast(fmaf(in0, w1r0.x, fmaf(in1, w1r1.x, fmaf(conv, w1r2.x, b1.x))));
            float h1 = tanh_fast(fmaf(in0, w1r0.y, fmaf(in1, w1r1.y, fmaf(conv, w1r2.y, b1.y))));
            float h2 = tanh_fast(fmaf(in0, w1r0.z, fmaf(in1, w1r1.z, fmaf(conv, w1r2.z, b1.z))));
            float h3 = tanh_fast(fmaf(in0, w1r0.w, fmaf(in1, w1r1.w, fmaf(conv, w1r2.w, b1.w))));

            float dz = fmaf(h0, g0, fmaf(h1, g1, fmaf(h2, g2, fmaf(h3, g3, gb))));
            float e = __expf(dz);
            float r = 1.0f / (1.0f + e);
            float o0 = r, o1 = e * r;

            if      (q == 0) { resA.x = o0; resA.y = o1; }
            else if (q == 1) { resA.z = o0; resA.w = o1; }
            else if (q == 2) { resB.x = o0; resB.y = o1; }
            else             { resB.z = o0; resB.w = o1; }
        }

        size_t ob = (size_t)tile * (TILE_SAMPLES / 2) + 2 * tid;
        __stcs(out + ob + 0, resA);
        __stcs(out + ob + 1, resB);

        // all threads done with slot s -> safe to refill
        __syncthreads();
        if (tid == 0) {
            int nt = tile + STAGES * gridDim.x;
            if (nt < ntiles) {
                uint32_t mb = mbar0 + 8u * s;
                uint32_t dst = sbase + SMEM_DATA_OFF + s * STAGE_BYTES;
                mbar_expect_tx(mb, STAGE_BYTES);
                bulk_g2s(dst,             inp  + (size_t)nt * (TILE_SAMPLES / 2), INP_BYTES,  mb);
                bulk_g2s(dst + INP_BYTES, data + (size_t)nt * TILE_SAMPLES,       DATA_BYTES, mb);
            }
        }
    }
}

extern "C" void kernel_launch(void* const* d_in, const int* in_sizes, int n_in,
                              void* d_out, int out_size)
{
    const float* inp    = (const float*)d_in[0]; // [B,2]
    const float* data   = (const float*)d_in[1]; // [B,2,2]
    const float* conv_w = (const float*)d_in[2];
    const float* conv_b = (const float*)d_in[3];
    const float* w1     = (const float*)d_in[4];
    const float* b1     = (const float*)d_in[5];
    const float* w2     = (const float*)d_in[6];
    const float* b2     = (const float*)d_in[7];
    float* out          = (float*)d_out;

    int B = in_sizes[0] / 2;              // samples (2^22)
    int ntiles = B / TILE_SAMPLES;        // 4096

    static bool attr_set = false;
    if (!attr_set) {
        cudaFuncSetAttribute(hybrid_sampler_kernel,
                             cudaFuncAttributeMaxDynamicSharedMemorySize, SMEM_TOTAL);
        attr_set = true;
    }

    // Persistent grid: 3 CTAs per SM (smem permitting; HW places as it fits).
    int blocks = 152 * 3;                 // 456

    hybrid_sampler_kernel<<<blocks, THREADS, SMEM_TOTAL>>>(
        (const float4*)inp, (const float4*)data,
        (const float4*)conv_w, conv_b,
        (const float4*)w1, (const float4*)b1,
        (const float4*)w2, (const float2*)b2,
        (float4*)out, ntiles);
}

// round 17
// speedup vs baseline: 1.0077x; 1.0077x over previous
#include <cuda_runtime.h>
#include <cstdint>

// Fused HybridSamplerConv, round 16: R15 early-release TMA pipeline + the
// missing proxy fence. R15's rel_err 2e-3 was a generic->async proxy race:
// consumer LDS reads of slot s must be ordered before the refill
// cp.async.bulk (async proxy) by fence.proxy.async.shared::cta executed by
// the issuing thread AFTER __syncthreads. R14 only passed because the
// compute phase between read and refill masked the same missing fence.

#define THREADS        256
#define STAGES         3
#define TILE_SAMPLES   1024
#define INP_BYTES      (TILE_SAMPLES * 8)        // 8192
#define DATA_BYTES     (TILE_SAMPLES * 16)       // 16384
#define STAGE_BYTES    (INP_BYTES + DATA_BYTES)  // 24576
#define SMEM_DATA_OFF  128
#define SMEM_TOTAL     (SMEM_DATA_OFF + STAGES * STAGE_BYTES)

__device__ __forceinline__ uint32_t smem_u32(const void* p) {
    uint32_t a;
    asm("{ .reg .u64 t; cvta.to.shared.u64 t, %1; cvt.u32.u64 %0, t; }"
        : "=r"(a) : "l"(p));
    return a;
}

__device__ __forceinline__ void mbar_init(uint32_t mbar, uint32_t count) {
    asm volatile("mbarrier.init.shared.b64 [%0], %1;" :: "r"(mbar), "r"(count) : "memory");
}

__device__ __forceinline__ void mbar_expect_tx(uint32_t mbar, uint32_t bytes) {
    asm volatile("mbarrier.arrive.expect_tx.shared.b64 _, [%0], %1;"
                 :: "r"(mbar), "r"(bytes) : "memory");
}

__device__ __forceinline__ void bulk_g2s(uint32_t smem_dst, const void* gmem_src,
                                         uint32_t bytes, uint32_t mbar) {
    asm volatile("cp.async.bulk.shared::cta.global.mbarrier::complete_tx::bytes "
                 "[%0], [%1], %2, [%3];"
                 :: "r"(smem_dst), "l"(gmem_src), "r"(bytes), "r"(mbar) : "memory");
}

__device__ __forceinline__ void mbar_wait(uint32_t mbar, uint32_t parity) {
    asm volatile(
        "{\n\t"
        ".reg .pred P;\n\t"
        "WAIT_%=: \n\t"
        "mbarrier.try_wait.parity.acquire.cta.shared::cta.b64 P, [%0], %1, 0x989680;\n\t"
        "@P bra.uni DONE_%=;\n\t"
        "bra.uni WAIT_%=;\n\t"
        "DONE_%=: \n\t"
        "}"
        :: "r"(mbar), "r"(parity) : "memory");
}

__device__ __forceinline__ void fence_proxy_async_cta() {
    asm volatile("fence.proxy.async.shared::cta;" ::: "memory");
}

__device__ __forceinline__ float tanh_fast(float x) {
    float y;
    asm("tanh.approx.f32 %0, %1;" : "=f"(y) : "f"(x));
    return y;
}

__global__ void __launch_bounds__(THREADS)
hybrid_sampler_kernel(const float4* __restrict__ inp,    // [B/2]
                      const float4* __restrict__ data,   // [B]
                      const float4* __restrict__ conv_w,
                      const float*  __restrict__ conv_b,
                      const float4* __restrict__ w1v,
                      const float4* __restrict__ b1v,
                      const float4* __restrict__ w2v,
                      const float2* __restrict__ b2v,
                      float4*       __restrict__ out,    // [B/2]
                      int ntiles)
{
    extern __shared__ char smem[];
    const uint32_t sbase = smem_u32(smem);
    const uint32_t mbar0 = sbase;
    const int tid = threadIdx.x;

    if (tid == 0) {
#pragma unroll
        for (int s = 0; s < STAGES; ++s) mbar_init(mbar0 + 8u * s, 1);
        fence_proxy_async_cta();
    }
    __syncthreads();

    // ---- uniform params ----
    float4 cw   = __ldg(conv_w);
    float  cb   = __ldg(conv_b);
    float4 w1r0 = __ldg(w1v + 0);
    float4 w1r1 = __ldg(w1v + 1);
    float4 w1r2 = __ldg(w1v + 2);
    float4 b1   = __ldg(b1v);
    float g0, g1, g2, g3, gb;
    {
        float4 w2a = __ldg(w2v + 0);
        float4 w2b = __ldg(w2v + 1);
        float2 b2  = __ldg(b2v);
        g0 = w2a.y - w2a.x;
        g1 = w2a.w - w2a.z;
        g2 = w2b.y - w2b.x;
        g3 = w2b.w - w2b.z;
        gb = b2.y  - b2.x;
    }

    // ---- prologue: fill all stages ----
    if (tid == 0) {
#pragma unroll
        for (int s = 0; s < STAGES; ++s) {
            int t = blockIdx.x + s * gridDim.x;
            if (t < ntiles) {
                uint32_t mb = mbar0 + 8u * s;
                uint32_t dst = sbase + SMEM_DATA_OFF + s * STAGE_BYTES;
                mbar_expect_tx(mb, STAGE_BYTES);
                bulk_g2s(dst,             inp  + (size_t)t * (TILE_SAMPLES / 2), INP_BYTES,  mb);
                bulk_g2s(dst + INP_BYTES, data + (size_t)t * TILE_SAMPLES,       DATA_BYTES, mb);
            }
        }
    }

    // ---- main loop: carried stage counter + parity ----
    int s = 0;
    uint32_t parity = 0;
    for (int tile = blockIdx.x; tile < ntiles; tile += gridDim.x) {
        mbar_wait(mbar0 + 8u * s, parity);

        const float4* sinp = (const float4*)(smem + SMEM_DATA_OFF + s * STAGE_BYTES);
        const float4* sdat = (const float4*)(smem + SMEM_DATA_OFF + s * STAGE_BYTES + INP_BYTES);

        // consume slot into registers
        float4 inA = sinp[2 * tid + 0];
        float4 inB = sinp[2 * tid + 1];
        float4 d0  = sdat[4 * tid + 0];
        float4 d1  = sdat[4 * tid + 1];
        float4 d2  = sdat[4 * tid + 2];
        float4 d3  = sdat[4 * tid + 3];

        // EARLY RELEASE with correct proxy ordering:
        // barrier gives thread 0 happens-before over all slot-s reads;
        // fence orders those generic accesses before the async-proxy refill.
        __syncthreads();
        if (tid == 0) {
            int nt = tile + STAGES * gridDim.x;
            if (nt < ntiles) {
                fence_proxy_async_cta();
                uint32_t mb = mbar0 + 8u * s;
                uint32_t dst = sbase + SMEM_DATA_OFF + s * STAGE_BYTES;
                mbar_expect_tx(mb, STAGE_BYTES);
                bulk_g2s(dst,             inp  + (size_t)nt * (TILE_SAMPLES / 2), INP_BYTES,  mb);
                bulk_g2s(dst + INP_BYTES, data + (size_t)nt * TILE_SAMPLES,       DATA_BYTES, mb);
            }
        }

        float4 resA, resB;
#pragma unroll
        for (int q = 0; q < 4; ++q) {
            float in0, in1;
            float4 d;
            if      (q == 0) { in0 = inA.x; in1 = inA.y; d = d0; }
            else if (q == 1) { in0 = inA.z; in1 = inA.w; d = d1; }
            else if (q == 2) { in0 = inB.x; in1 = inB.y; d = d2; }
            else             { in0 = inB.z; in1 = inB.w; d = d3; }

            float logit = fmaf(d.x, cw.x, fmaf(d.y, cw.y,
                          fmaf(d.z, cw.z, fmaf(d.w, cw.w, cb))));
            float conv = fmaf(tanh_fast(0.5f * logit), 0.5f, 0.5f);

            float h0 = tanh_fast(fmaf(in0, w1r0.x, fmaf(in1, w1r1.x, fmaf(conv, w1r2.x, b1.x))));
            float h1 = tanh_fast(fmaf(in0, w1r0.y, fmaf(in1, w1r1.y, fmaf(conv, w1r2.y, b1.y))));
            float h2 = tanh_fast(fmaf(in0, w1r0.z, fmaf(in1, w1r1.z, fmaf(conv, w1r2.z, b1.z))));
            float h3 = tanh_fast(fmaf(in0, w1r0.w, fmaf(in1, w1r1.w, fmaf(conv, w1r2.w, b1.w))));

            float dz = fmaf(h0, g0, fmaf(h1, g1, fmaf(h2, g2, fmaf(h3, g3, gb))));
            float e = __expf(dz);
            float r = 1.0f / (1.0f + e);
            float o0 = r, o1 = e * r;

            if      (q == 0) { resA.x = o0; resA.y = o1; }
            else if (q == 1) { resA.z = o0; resA.w = o1; }
            else if (q == 2) { resB.x = o0; resB.y = o1; }
            else             { resB.z = o0; resB.w = o1; }
        }

        size_t ob = (size_t)tile * (TILE_SAMPLES / 2) + 2 * tid;
        __stcs(out + ob + 0, resA);
        __stcs(out + ob + 1, resB);

        ++s;
        if (s == STAGES) { s = 0; parity ^= 1u; }
    }
}

extern "C" void kernel_launch(void* const* d_in, const int* in_sizes, int n_in,
                              void* d_out, int out_size)
{
    const float* inp    = (const float*)d_in[0];
    const float* data   = (const float*)d_in[1];
    const float* conv_w = (const float*)d_in[2];
    const float* conv_b = (const float*)d_in[3];
    const float* w1     = (const float*)d_in[4];
    const float* b1     = (const float*)d_in[5];
    const float* w2     = (const float*)d_in[6];
    const float* b2     = (const float*)d_in[7];
    float* out          = (float*)d_out;

    int B = in_sizes[0] / 2;           // samples (2^22)
    int ntiles = B / TILE_SAMPLES;     // 4096

    static bool attr_set = false;
    if (!attr_set) {
        cudaFuncSetAttribute(hybrid_sampler_kernel,
                             cudaFuncAttributeMaxDynamicSharedMemorySize, SMEM_TOTAL);
        attr_set = true;
    }

    int blocks = 152 * 3;              // 3 CTAs/SM (smem-limited)

    hybrid_sampler_kernel<<<blocks, THREADS, SMEM_TOTAL>>>(
        (const float4*)inp, (const float4*)data,
        (const float4*)conv_w, conv_b,
        (const float4*)w1, (const float4*)b1,
        (const float4*)w2, (const float2*)b2,
        (float4*)out, ntiles);
}